// round 4
// baseline (speedup 1.0000x reference)
#include <cuda_runtime.h>
#include <math.h>

// Problem constants
#define VV    32000
#define EE    256
#define DD    25
#define BB    64
#define TT    24
#define HH    625          // D*D
#define INDIM 906          // E + H + D
#define KTOT  1556         // IN + H(hS) + D(hU)
#define KP    1600         // padded K for gate GEMM
#define NG    2600         // 4H + 4D gate rows (S rows 0..2499, U rows 2500..2599)
#define NSTEPS 23
#define KFC   640          // padded 625 for final GEMM
#define NBS   260          // persistent blocks: 2 k-splits x 130 n-tiles

// ---------------- static device scratch (zero-initialized at load) ----------
__device__ float g_Wcat[NG * KP];           // packed [WihS|WhhS|0] / [WihU|0|WhhU]
__device__ float g_bias[NG];                // bih + bhh
__device__ float g_fcWp[VV * KFC];          // fcW padded to K=640
__device__ float g_xh[BB * KP];             // [cU(25)|word(256)|cS(625)|hS(625)|hU(25)|pad]
__device__ float g_gP[2][BB * NG];          // split-K gate partials
__device__ float g_cS[BB * HH];
__device__ float g_cU[BB * DD];
__device__ float g_ft[TT * BB * KFC];       // row block t=0 and pad cols NEVER written -> stay 0
__device__ unsigned int g_bar;

__device__ __forceinline__ float sigmoidf_(float x) { return 1.f / (1.f + expf(-x)); }

__device__ __forceinline__ void grid_sync_() {
    __syncthreads();
    if (threadIdx.x == 0) {
        __threadfence();
        unsigned int t = atomicAdd(&g_bar, 1u);
        unsigned int target = t - (t % NBS) + NBS;
        volatile unsigned int* p = &g_bar;
        while ((int)(*p - target) < 0) { }
    }
    __syncthreads();
}

// ---------------- weight packing -------------------------------------------
__global__ void pack_kernel(const float* __restrict__ WihS, const float* __restrict__ WhhS,
                            const float* __restrict__ bihS, const float* __restrict__ bhhS,
                            const float* __restrict__ WihU, const float* __restrict__ WhhU,
                            const float* __restrict__ bihU, const float* __restrict__ bhhU,
                            const float* __restrict__ fcW) {
    const long long n_wcat = (long long)NG * KP;
    const long long n_fc   = (long long)VV * KFC;
    const long long total  = n_wcat + n_fc + NG;
    for (long long i = blockIdx.x * (long long)blockDim.x + threadIdx.x; i < total;
         i += (long long)gridDim.x * blockDim.x) {
        if (i < n_wcat) {
            int n = (int)(i / KP), k = (int)(i % KP);
            float v = 0.f;
            if (n < 4 * HH) {
                if (k < INDIM)            v = WihS[n * INDIM + k];
                else if (k < INDIM + HH)  v = WhhS[n * HH + (k - INDIM)];
                // hU slot + pad: 0
            } else {
                int nu = n - 4 * HH;
                if (k < INDIM)                          v = WihU[nu * INDIM + k];
                else if (k >= INDIM + HH && k < KTOT)   v = WhhU[nu * DD + (k - INDIM - HH)];
            }
            g_Wcat[i] = v;
        } else if (i < n_wcat + n_fc) {
            long long j = i - n_wcat;
            int k = (int)(j % KFC);
            int n = (int)(j / KFC);
            g_fcWp[j] = (k < HH) ? fcW[(long long)n * HH + k] : 0.f;
        } else {
            int n = (int)(i - n_wcat - n_fc);
            g_bias[n] = (n < 4 * HH) ? (bihS[n] + bhhS[n]) : (bihU[n - 4 * HH] + bhhU[n - 4 * HH]);
        }
    }
}

// ---------------- initial state --------------------------------------------
// block b: sStart = features[b] @ szW.T + szb ; build xh row for step 0
__global__ void init_kernel(const float* __restrict__ features, const float* __restrict__ embed,
                            const float* __restrict__ szW, const float* __restrict__ szb) {
    __shared__ float sf[EE];
    const int b = blockIdx.x, tid = threadIdx.x;
    sf[tid] = features[b * EE + tid];       // blockDim == 256 == EE
    __syncthreads();
    float* xh = g_xh + b * KP;
    for (int c = tid; c < HH; c += 256) {
        float acc = szb[c];
        const float* w = szW + c * EE;
        #pragma unroll 8
        for (int k = 0; k < EE; k++) acc += sf[k] * w[k];
        g_cS[b * HH + c] = acc;
        xh[281 + c] = acc;   // cS slot (25+256=281)
        xh[906 + c] = 0.f;   // hS = 0
    }
    if (tid < DD) {
        g_cU[b * DD + tid] = 0.f;
        xh[tid] = 0.f;          // cU slot (zeros for fIn)
        xh[1531 + tid] = 0.f;   // hU = 0
    }
    xh[25 + tid] = embed[tid];  // word0 = embed_table[0]
    if (tid < KP - KTOT) xh[KTOT + tid] = 0.f;  // pad
}

// ---------------- persistent recurrence ------------------------------------
// grid = 260 blocks x 128 threads, custom grid barrier between phases.
// Phase A: g_gP[kt] = xh[:, kt*800 : +800] @ Wcat[:, same].T   (tiles of 20 gate rows)
// Phase B: blocks 0..63 (one per batch) apply LSTM cells, rebuild xh, compute ft.
__global__ void __launch_bounds__(128, 2)
steps_kernel(const int* __restrict__ captions, const float* __restrict__ embed,
             const float* __restrict__ wuW, const float* __restrict__ wub) {
    __shared__ float sx[64][33];
    __shared__ float sw[20][32];
    __shared__ float shS[HH];
    __shared__ float shU[DD];
    __shared__ float sut[HH];

    const int tid  = threadIdx.x;
    const int kt   = blockIdx.x & 1;        // K half
    const int tile = blockIdx.x >> 1;       // 0..129
    const int n0   = tile * 20;
    const int m0   = tid & 31;              // rows m0, m0+32
    const int ng   = tid >> 5;              // 0..3 -> 5 cols each

    for (int s = 0; s < NSTEPS; s++) {
        // ---------- phase A ----------
        float acc0[5] = {0,0,0,0,0}, acc1[5] = {0,0,0,0,0};
        const int kbase0 = kt * 800;
        for (int ch = 0; ch < 25; ch++) {
            const int kb = kbase0 + ch * 32;
            __syncthreads();
            #pragma unroll
            for (int q = tid; q < 512; q += 128) {            // xh tile 64x32 (L2, fresh)
                int r = q >> 3, c4 = q & 7;
                float4 v = __ldcg((const float4*)(g_xh + r * KP + kb + c4 * 4));
                sx[r][c4*4+0] = v.x; sx[r][c4*4+1] = v.y; sx[r][c4*4+2] = v.z; sx[r][c4*4+3] = v.w;
            }
            for (int q = tid; q < 160; q += 128) {            // W tile 20x32 (immutable, L1-warm)
                int r = q >> 3, c4 = q & 7;
                float4 v = *(const float4*)(g_Wcat + (n0 + r) * KP + kb + c4 * 4);
                sw[r][c4*4+0] = v.x; sw[r][c4*4+1] = v.y; sw[r][c4*4+2] = v.z; sw[r][c4*4+3] = v.w;
            }
            __syncthreads();
            #pragma unroll
            for (int kk = 0; kk < 32; kk++) {
                float x0 = sx[m0][kk], x1 = sx[m0 + 32][kk];
                #pragma unroll
                for (int j = 0; j < 5; j++) {
                    float w = sw[ng * 5 + j][kk];
                    acc0[j] += x0 * w;
                    acc1[j] += x1 * w;
                }
            }
        }
        {
            float* dst = g_gP[kt];
            #pragma unroll
            for (int j = 0; j < 5; j++) {
                dst[m0 * NG + n0 + ng * 5 + j]        = acc0[j];
                dst[(m0 + 32) * NG + n0 + ng * 5 + j] = acc1[j];
            }
        }
        grid_sync_();

        // ---------- phase B ----------
        if (blockIdx.x < BB) {
            const int b = blockIdx.x;
            const float* p0 = g_gP[0] + b * NG;
            const float* p1 = g_gP[1] + b * NG;
            float* xh = g_xh + b * KP;
            for (int e = tid; e < HH; e += 128) {
                float gi = __ldcg(p0 + e)          + __ldcg(p1 + e)          + g_bias[e];
                float gf = __ldcg(p0 + HH + e)     + __ldcg(p1 + HH + e)     + g_bias[HH + e];
                float gg = __ldcg(p0 + 2*HH + e)   + __ldcg(p1 + 2*HH + e)   + g_bias[2*HH + e];
                float go = __ldcg(p0 + 3*HH + e)   + __ldcg(p1 + 3*HH + e)   + g_bias[3*HH + e];
                float c = sigmoidf_(gf) * g_cS[b * HH + e] + sigmoidf_(gi) * tanhf(gg);
                float h = sigmoidf_(go) * tanhf(c);
                g_cS[b * HH + e] = c;
                shS[e] = h;
                xh[281 + e] = c;   // x.cS for next step
                xh[906 + e] = h;   // hS
            }
            if (tid < DD) {
                const int e = tid, u = 4 * HH;
                float gi = __ldcg(p0 + u + e)        + __ldcg(p1 + u + e)        + g_bias[u + e];
                float gf = __ldcg(p0 + u + 25 + e)   + __ldcg(p1 + u + 25 + e)   + g_bias[u + 25 + e];
                float gg = __ldcg(p0 + u + 50 + e)   + __ldcg(p1 + u + 50 + e)   + g_bias[u + 50 + e];
                float go = __ldcg(p0 + u + 75 + e)   + __ldcg(p1 + u + 75 + e)   + g_bias[u + 75 + e];
                float c = sigmoidf_(gf) * g_cU[b * DD + e] + sigmoidf_(gi) * tanhf(gg);
                float h = sigmoidf_(go) * tanhf(c);
                g_cU[b * DD + e] = c;
                shU[e] = h;
                xh[e] = c;          // x.cU for next step
                xh[1531 + e] = h;   // hU
            }
            if (s + 1 < NSTEPS) {   // next word: embed_table[captions[b][s+1]]
                const int w = captions[b * TT + (s + 1)];
                for (int e = tid; e < EE; e += 128) xh[25 + e] = embed[w * EE + e];
            }
            __syncthreads();
            for (int p = tid; p < HH; p += 128) {   // ut = hU @ wuW.T + wub
                float acc = wub[p];
                const float* r = wuW + p * DD;
                #pragma unroll
                for (int d2 = 0; d2 < DD; d2++) acc += shU[d2] * r[d2];
                sut[p] = acc;
            }
            __syncthreads();
            float* ftrow = g_ft + ((s + 1) * BB + b) * KFC;   // ft = ut(25x25) @ hS(25x25)
            for (int idx = tid; idx < HH; idx += 128) {
                int i2 = idx / DD, j2 = idx - i2 * DD;
                float acc = 0.f;
                #pragma unroll
                for (int k2 = 0; k2 < DD; k2++) acc += sut[i2 * DD + k2] * shS[k2 * DD + j2];
                ftrow[idx] = acc;
            }
        }
        grid_sync_();
    }
}

// ---------------- final projection: out[m,n] = ft[m] . fcW[n] + fcb[n] ------
// 128x128 tile, 256 threads, 8x8 microtile, K chunks of 16.
__global__ void __launch_bounds__(256, 2)
fc_kernel(const float* __restrict__ fcb, float* __restrict__ out) {
    __shared__ float As[16][128];
    __shared__ float Bs[16][128];
    const int tid = threadIdx.x;
    const int tx = tid & 15, ty = tid >> 4;
    const int m0 = blockIdx.y * 128;
    const int n0 = blockIdx.x * 128;
    float acc[8][8];
    #pragma unroll
    for (int i = 0; i < 8; i++)
        #pragma unroll
        for (int j = 0; j < 8; j++) acc[i][j] = 0.f;

    for (int k0 = 0; k0 < KFC; k0 += 16) {
        #pragma unroll
        for (int q = tid; q < 512; q += 256) {
            int r = q >> 2, c4 = q & 3;
            float4 v = *(const float4*)(g_ft + (m0 + r) * KFC + k0 + c4 * 4);
            As[c4*4+0][r] = v.x; As[c4*4+1][r] = v.y; As[c4*4+2][r] = v.z; As[c4*4+3][r] = v.w;
        }
        #pragma unroll
        for (int q = tid; q < 512; q += 256) {
            int r = q >> 2, c4 = q & 3;
            float4 v = *(const float4*)(g_fcWp + (n0 + r) * KFC + k0 + c4 * 4);
            Bs[c4*4+0][r] = v.x; Bs[c4*4+1][r] = v.y; Bs[c4*4+2][r] = v.z; Bs[c4*4+3][r] = v.w;
        }
        __syncthreads();
        #pragma unroll
        for (int kk = 0; kk < 16; kk++) {
            float a[8], bb[8];
            *(float4*)&a[0]  = *(const float4*)&As[kk][ty * 8];
            *(float4*)&a[4]  = *(const float4*)&As[kk][ty * 8 + 4];
            *(float4*)&bb[0] = *(const float4*)&Bs[kk][tx * 8];
            *(float4*)&bb[4] = *(const float4*)&Bs[kk][tx * 8 + 4];
            #pragma unroll
            for (int i = 0; i < 8; i++)
                #pragma unroll
                for (int j = 0; j < 8; j++) acc[i][j] += a[i] * bb[j];
        }
        __syncthreads();
    }
    float bb[8];
    #pragma unroll
    for (int j = 0; j < 8; j++) bb[j] = fcb[n0 + tx * 8 + j];
    #pragma unroll
    for (int i = 0; i < 8; i++) {
        float4 v0, v1;
        v0.x = acc[i][0] + bb[0]; v0.y = acc[i][1] + bb[1];
        v0.z = acc[i][2] + bb[2]; v0.w = acc[i][3] + bb[3];
        v1.x = acc[i][4] + bb[4]; v1.y = acc[i][5] + bb[5];
        v1.z = acc[i][6] + bb[6]; v1.w = acc[i][7] + bb[7];
        float* dst = out + (long long)(m0 + ty * 8 + i) * VV + n0 + tx * 8;
        *(float4*)dst       = v0;
        *(float4*)(dst + 4) = v1;
    }
}

// ---------------- launch ----------------------------------------------------
extern "C" void kernel_launch(void* const* d_in, const int* in_sizes, int n_in,
                              void* d_out, int out_size) {
    (void)in_sizes; (void)n_in; (void)out_size;
    const float* features = (const float*)d_in[0];
    const int*   captions = (const int*)  d_in[1];
    const float* embed    = (const float*)d_in[2];
    const float* WihS     = (const float*)d_in[3];
    const float* WhhS     = (const float*)d_in[4];
    const float* bihS     = (const float*)d_in[5];
    const float* bhhS     = (const float*)d_in[6];
    const float* WihU     = (const float*)d_in[7];
    const float* WhhU     = (const float*)d_in[8];
    const float* bihU     = (const float*)d_in[9];
    const float* bhhU     = (const float*)d_in[10];
    const float* fcW      = (const float*)d_in[11];
    const float* fcb      = (const float*)d_in[12];
    const float* szW      = (const float*)d_in[13];
    const float* szb      = (const float*)d_in[14];
    const float* wuW      = (const float*)d_in[15];
    const float* wub      = (const float*)d_in[16];
    float* out = (float*)d_out;

    pack_kernel<<<2048, 256>>>(WihS, WhhS, bihS, bhhS, WihU, WhhU, bihU, bhhU, fcW);
    init_kernel<<<BB, 256>>>(features, embed, szW, szb);
    steps_kernel<<<NBS, 128>>>(captions, embed, wuW, wub);
    fc_kernel<<<dim3(VV / 128, (TT * BB) / 128), 256>>>(fcb, out);
}

// round 5
// speedup vs baseline: 1.9140x; 1.9140x over previous
#include <cuda_runtime.h>
#include <cuda_bf16.h>
#include <math.h>

// Problem constants
#define VV    32000
#define EE    256
#define DD    25
#define BB    64
#define TT    24
#define HH    625          // D*D
#define INDIM 906          // E + H + D
#define KTOT  1556         // IN + H(hS) + D(hU)
#define KP    1600         // padded K for gate GEMM
#define NG    2600         // 4H + 4D gate rows
#define NSTEPS 23
#define KFC   640          // padded 625 for final GEMM
#define NBS   260          // persistent blocks: 2 k-splits x 130 n-tiles

// ---------------- static device scratch (zero-initialized at load) ----------
__device__ float g_Wcat[NG * KP];
__device__ float g_bias[NG];
__device__ unsigned short g_fcWh[VV * KFC];   // fcW bf16 hi
__device__ unsigned short g_fcWl[VV * KFC];   // fcW bf16 lo (residual)
__device__ float g_xh[BB * KP];               // [cU|word|cS|hS|hU|pad]
__device__ float g_gP[2][BB * NG];
__device__ float g_cS[BB * HH];
__device__ float g_cU[BB * DD];
__device__ unsigned short g_fth[TT * BB * KFC];  // ft bf16 hi (t=0 + pad stay 0)
__device__ unsigned short g_ftl[TT * BB * KFC];  // ft bf16 lo
__device__ unsigned int g_bar;

__device__ __forceinline__ float sigmoidf_(float x) { return 1.f / (1.f + expf(-x)); }

__device__ __forceinline__ unsigned short f2bf(float v) {
    __nv_bfloat16 b = __float2bfloat16(v);
    return *reinterpret_cast<unsigned short*>(&b);
}
__device__ __forceinline__ float bf2f(unsigned short u) {
    __nv_bfloat16 b;
    *reinterpret_cast<unsigned short*>(&b) = u;
    return __bfloat162float(b);
}

__device__ __forceinline__ void grid_sync_() {
    __syncthreads();
    if (threadIdx.x == 0) {
        __threadfence();
        unsigned int t = atomicAdd(&g_bar, 1u);
        unsigned int target = t - (t % NBS) + NBS;
        volatile unsigned int* p = &g_bar;
        while ((int)(*p - target) < 0) { }
    }
    __syncthreads();
}

__device__ __forceinline__ void cp16(void* sdst, const void* gsrc) {
    unsigned saddr = (unsigned)__cvta_generic_to_shared(sdst);
    asm volatile("cp.async.cg.shared.global [%0], [%1], 16;" :: "r"(saddr), "l"(gsrc));
}

__device__ __forceinline__ void mma_bf16(float c[4], unsigned a0, unsigned a1,
                                         unsigned a2, unsigned a3,
                                         unsigned b0, unsigned b1) {
    asm volatile(
        "mma.sync.aligned.m16n8k16.row.col.f32.bf16.bf16.f32 "
        "{%0,%1,%2,%3},{%4,%5,%6,%7},{%8,%9},{%0,%1,%2,%3};"
        : "+f"(c[0]), "+f"(c[1]), "+f"(c[2]), "+f"(c[3])
        : "r"(a0), "r"(a1), "r"(a2), "r"(a3), "r"(b0), "r"(b1));
}

// ---------------- weight packing -------------------------------------------
__global__ void pack_kernel(const float* __restrict__ WihS, const float* __restrict__ WhhS,
                            const float* __restrict__ bihS, const float* __restrict__ bhhS,
                            const float* __restrict__ WihU, const float* __restrict__ WhhU,
                            const float* __restrict__ bihU, const float* __restrict__ bhhU,
                            const float* __restrict__ fcW) {
    const long long n_wcat = (long long)NG * KP;
    const long long n_fc   = (long long)VV * KFC;
    const long long total  = n_wcat + n_fc + NG;
    for (long long i = blockIdx.x * (long long)blockDim.x + threadIdx.x; i < total;
         i += (long long)gridDim.x * blockDim.x) {
        if (i < n_wcat) {
            int n = (int)(i / KP), k = (int)(i % KP);
            float v = 0.f;
            if (n < 4 * HH) {
                if (k < INDIM)            v = WihS[n * INDIM + k];
                else if (k < INDIM + HH)  v = WhhS[n * HH + (k - INDIM)];
            } else {
                int nu = n - 4 * HH;
                if (k < INDIM)                          v = WihU[nu * INDIM + k];
                else if (k >= INDIM + HH && k < KTOT)   v = WhhU[nu * DD + (k - INDIM - HH)];
            }
            g_Wcat[i] = v;
        } else if (i < n_wcat + n_fc) {
            long long j = i - n_wcat;
            int k = (int)(j % KFC);
            int n = (int)(j / KFC);
            float v = (k < HH) ? fcW[(long long)n * HH + k] : 0.f;
            unsigned short h = f2bf(v);
            g_fcWh[j] = h;
            g_fcWl[j] = f2bf(v - bf2f(h));
        } else {
            int n = (int)(i - n_wcat - n_fc);
            g_bias[n] = (n < 4 * HH) ? (bihS[n] + bhhS[n]) : (bihU[n - 4 * HH] + bhhU[n - 4 * HH]);
        }
    }
}

// ---------------- initial state --------------------------------------------
__global__ void init_kernel(const float* __restrict__ features, const float* __restrict__ embed,
                            const float* __restrict__ szW, const float* __restrict__ szb) {
    __shared__ float sf[EE];
    const int b = blockIdx.x, tid = threadIdx.x;
    sf[tid] = features[b * EE + tid];
    __syncthreads();
    float* xh = g_xh + b * KP;
    for (int c = tid; c < HH; c += 256) {
        float acc = szb[c];
        const float* w = szW + c * EE;
        #pragma unroll 8
        for (int k = 0; k < EE; k++) acc += sf[k] * w[k];
        g_cS[b * HH + c] = acc;
        xh[281 + c] = acc;
        xh[906 + c] = 0.f;
    }
    if (tid < DD) {
        g_cU[b * DD + tid] = 0.f;
        xh[tid] = 0.f;
        xh[1531 + tid] = 0.f;
    }
    xh[25 + tid] = embed[tid];
    if (tid < KP - KTOT) xh[KTOT + tid] = 0.f;
}

// ---------------- persistent recurrence ------------------------------------
__global__ void __launch_bounds__(128, 2)
steps_kernel(const int* __restrict__ captions, const float* __restrict__ embed,
             const float* __restrict__ wuW, const float* __restrict__ wub) {
    __shared__ float sx[64][33];
    __shared__ float sw[20][32];
    __shared__ float shS[HH];
    __shared__ float shU[DD];
    __shared__ float sut[HH];

    const int tid  = threadIdx.x;
    const int kt   = blockIdx.x & 1;
    const int tile = blockIdx.x >> 1;
    const int n0   = tile * 20;
    const int m0   = tid & 31;
    const int ng   = tid >> 5;
    const int rx   = tid >> 3, cx = (tid & 7) * 4;   // load coords (sx/sw)
    const bool hasW1 = (tid < 32);

    for (int s = 0; s < NSTEPS; s++) {
        // ---------- phase A (register-prefetch double-buffered) ----------
        float acc0[5] = {0,0,0,0,0}, acc1[5] = {0,0,0,0,0};
        const int kbase0 = kt * 800;

        float4 vx0, vx1, vx2, vx3, vw0, vw1;
        {
            const int kb = kbase0;
            vx0 = __ldcg((const float4*)(g_xh + (rx      ) * KP + kb + cx));
            vx1 = __ldcg((const float4*)(g_xh + (rx + 16 ) * KP + kb + cx));
            vx2 = __ldcg((const float4*)(g_xh + (rx + 32 ) * KP + kb + cx));
            vx3 = __ldcg((const float4*)(g_xh + (rx + 48 ) * KP + kb + cx));
            vw0 = *(const float4*)(g_Wcat + (n0 + rx) * KP + kb + cx);
            if (hasW1) vw1 = *(const float4*)(g_Wcat + (n0 + 16 + rx) * KP + kb + cx);
        }

        for (int ch = 0; ch < 25; ch++) {
            __syncthreads();
            sx[rx     ][cx+0]=vx0.x; sx[rx     ][cx+1]=vx0.y; sx[rx     ][cx+2]=vx0.z; sx[rx     ][cx+3]=vx0.w;
            sx[rx + 16][cx+0]=vx1.x; sx[rx + 16][cx+1]=vx1.y; sx[rx + 16][cx+2]=vx1.z; sx[rx + 16][cx+3]=vx1.w;
            sx[rx + 32][cx+0]=vx2.x; sx[rx + 32][cx+1]=vx2.y; sx[rx + 32][cx+2]=vx2.z; sx[rx + 32][cx+3]=vx2.w;
            sx[rx + 48][cx+0]=vx3.x; sx[rx + 48][cx+1]=vx3.y; sx[rx + 48][cx+2]=vx3.z; sx[rx + 48][cx+3]=vx3.w;
            sw[rx][cx+0]=vw0.x; sw[rx][cx+1]=vw0.y; sw[rx][cx+2]=vw0.z; sw[rx][cx+3]=vw0.w;
            if (hasW1) {
                sw[16+rx][cx+0]=vw1.x; sw[16+rx][cx+1]=vw1.y; sw[16+rx][cx+2]=vw1.z; sw[16+rx][cx+3]=vw1.w;
            }
            __syncthreads();
            if (ch < 24) {
                const int kb = kbase0 + (ch + 1) * 32;
                vx0 = __ldcg((const float4*)(g_xh + (rx      ) * KP + kb + cx));
                vx1 = __ldcg((const float4*)(g_xh + (rx + 16 ) * KP + kb + cx));
                vx2 = __ldcg((const float4*)(g_xh + (rx + 32 ) * KP + kb + cx));
                vx3 = __ldcg((const float4*)(g_xh + (rx + 48 ) * KP + kb + cx));
                vw0 = *(const float4*)(g_Wcat + (n0 + rx) * KP + kb + cx);
                if (hasW1) vw1 = *(const float4*)(g_Wcat + (n0 + 16 + rx) * KP + kb + cx);
            }
            #pragma unroll
            for (int kk = 0; kk < 32; kk++) {
                float x0 = sx[m0][kk], x1 = sx[m0 + 32][kk];
                #pragma unroll
                for (int j = 0; j < 5; j++) {
                    float w = sw[ng * 5 + j][kk];
                    acc0[j] += x0 * w;
                    acc1[j] += x1 * w;
                }
            }
        }
        {
            float* dst = g_gP[kt];
            #pragma unroll
            for (int j = 0; j < 5; j++) {
                dst[m0 * NG + n0 + ng * 5 + j]        = acc0[j];
                dst[(m0 + 32) * NG + n0 + ng * 5 + j] = acc1[j];
            }
        }
        grid_sync_();

        // ---------- phase B ----------
        if (blockIdx.x < BB) {
            const int b = blockIdx.x;
            const float* p0 = g_gP[0] + b * NG;
            const float* p1 = g_gP[1] + b * NG;
            float* xh = g_xh + b * KP;
            for (int e = tid; e < HH; e += 128) {
                float gi = __ldcg(p0 + e)          + __ldcg(p1 + e)          + g_bias[e];
                float gf = __ldcg(p0 + HH + e)     + __ldcg(p1 + HH + e)     + g_bias[HH + e];
                float gg = __ldcg(p0 + 2*HH + e)   + __ldcg(p1 + 2*HH + e)   + g_bias[2*HH + e];
                float go = __ldcg(p0 + 3*HH + e)   + __ldcg(p1 + 3*HH + e)   + g_bias[3*HH + e];
                float c = sigmoidf_(gf) * g_cS[b * HH + e] + sigmoidf_(gi) * tanhf(gg);
                float h = sigmoidf_(go) * tanhf(c);
                g_cS[b * HH + e] = c;
                shS[e] = h;
                xh[281 + e] = c;
                xh[906 + e] = h;
            }
            if (tid < DD) {
                const int e = tid, u = 4 * HH;
                float gi = __ldcg(p0 + u + e)        + __ldcg(p1 + u + e)        + g_bias[u + e];
                float gf = __ldcg(p0 + u + 25 + e)   + __ldcg(p1 + u + 25 + e)   + g_bias[u + 25 + e];
                float gg = __ldcg(p0 + u + 50 + e)   + __ldcg(p1 + u + 50 + e)   + g_bias[u + 50 + e];
                float go = __ldcg(p0 + u + 75 + e)   + __ldcg(p1 + u + 75 + e)   + g_bias[u + 75 + e];
                float c = sigmoidf_(gf) * g_cU[b * DD + e] + sigmoidf_(gi) * tanhf(gg);
                float h = sigmoidf_(go) * tanhf(c);
                g_cU[b * DD + e] = c;
                shU[e] = h;
                xh[e] = c;
                xh[1531 + e] = h;
            }
            if (s + 1 < NSTEPS) {
                const int w = captions[b * TT + (s + 1)];
                for (int e = tid; e < EE; e += 128) xh[25 + e] = embed[w * EE + e];
            }
            __syncthreads();
            for (int p = tid; p < HH; p += 128) {
                float acc = wub[p];
                const float* r = wuW + p * DD;
                #pragma unroll
                for (int d2 = 0; d2 < DD; d2++) acc += shU[d2] * r[d2];
                sut[p] = acc;
            }
            __syncthreads();
            const long long base = (long long)((s + 1) * BB + b) * KFC;
            for (int idx = tid; idx < HH; idx += 128) {
                int i2 = idx / DD, j2 = idx - i2 * DD;
                float acc = 0.f;
                #pragma unroll
                for (int k2 = 0; k2 < DD; k2++) acc += sut[i2 * DD + k2] * shS[k2 * DD + j2];
                unsigned short h = f2bf(acc);
                g_fth[base + idx] = h;
                g_ftl[base + idx] = f2bf(acc - bf2f(h));
            }
        }
        grid_sync_();
    }
}

// ---------------- final projection on tensor cores --------------------------
// out[m,n] = ft[m,:] . fcW[n,:] + fcb[n], via bf16 hi/lo 3-term mma split.
// Block: 128M x 128N, 8 warps of 64x32, K-chunk 16, cp.async double-buffered.
#define FCSTR 24   // smem row stride in bf16 (48B: 16B-aligned, conflict-free frags)
__global__ void __launch_bounds__(256, 2)
fc_kernel(const float* __restrict__ fcb, float* __restrict__ out) {
    __shared__ unsigned short sAh[2][128 * FCSTR];
    __shared__ unsigned short sAl[2][128 * FCSTR];
    __shared__ unsigned short sBh[2][128 * FCSTR];
    __shared__ unsigned short sBl[2][128 * FCSTR];

    const int tid   = threadIdx.x;
    const int lane  = tid & 31;
    const int wid   = tid >> 5;
    const int g     = lane >> 2;        // group 0..7
    const int t4    = lane & 3;
    const int mbase = (wid & 1) * 64;
    const int nbase = (wid >> 1) * 32;
    const int m0    = blockIdx.y * 128;
    const int n0    = blockIdx.x * 128;

    const int lrow  = tid >> 1;         // 0..127
    const int lks   = (tid & 1) * 8;    // 0 or 8 (bf16 elems)

    float acc[4][4][4];
    #pragma unroll
    for (int mf = 0; mf < 4; mf++)
        #pragma unroll
        for (int nf = 0; nf < 4; nf++)
            #pragma unroll
            for (int r = 0; r < 4; r++) acc[mf][nf][r] = 0.f;

    const unsigned short* gAh = g_fth + (long long)(m0 + lrow) * KFC + lks;
    const unsigned short* gAl = g_ftl + (long long)(m0 + lrow) * KFC + lks;
    const unsigned short* gBh = g_fcWh + (long long)(n0 + lrow) * KFC + lks;
    const unsigned short* gBl = g_fcWl + (long long)(n0 + lrow) * KFC + lks;
    const int sOff = lrow * FCSTR + lks;

    // prologue: chunk 0 -> buf 0
    cp16(&sAh[0][sOff], gAh);
    cp16(&sAl[0][sOff], gAl);
    cp16(&sBh[0][sOff], gBh);
    cp16(&sBl[0][sOff], gBl);
    asm volatile("cp.async.commit_group;");

    for (int ch = 0; ch < 40; ch++) {
        if (ch < 39) {
            const int k0 = (ch + 1) * 16;
            const int buf = (ch + 1) & 1;
            cp16(&sAh[buf][sOff], gAh + k0);
            cp16(&sAl[buf][sOff], gAl + k0);
            cp16(&sBh[buf][sOff], gBh + k0);
            cp16(&sBl[buf][sOff], gBl + k0);
            asm volatile("cp.async.commit_group;");
            asm volatile("cp.async.wait_group 1;" ::: "memory");
        } else {
            asm volatile("cp.async.wait_group 0;" ::: "memory");
        }
        __syncthreads();

        const int buf = ch & 1;
        const unsigned short* Ah = sAh[buf];
        const unsigned short* Al = sAl[buf];
        const unsigned short* Bh = sBh[buf];
        const unsigned short* Bl = sBl[buf];

        unsigned bh[4][2], bl[4][2];
        #pragma unroll
        for (int nf = 0; nf < 4; nf++) {
            const int n = (nbase + nf * 8 + g) * FCSTR + t4 * 2;
            bh[nf][0] = *(const unsigned*)&Bh[n];
            bh[nf][1] = *(const unsigned*)&Bh[n + 8];
            bl[nf][0] = *(const unsigned*)&Bl[n];
            bl[nf][1] = *(const unsigned*)&Bl[n + 8];
        }
        #pragma unroll
        for (int mf = 0; mf < 4; mf++) {
            const int r = (mbase + mf * 16 + g) * FCSTR + t4 * 2;
            unsigned ah0 = *(const unsigned*)&Ah[r];
            unsigned ah1 = *(const unsigned*)&Ah[r + 8 * FCSTR];
            unsigned ah2 = *(const unsigned*)&Ah[r + 8];
            unsigned ah3 = *(const unsigned*)&Ah[r + 8 * FCSTR + 8];
            unsigned al0 = *(const unsigned*)&Al[r];
            unsigned al1 = *(const unsigned*)&Al[r + 8 * FCSTR];
            unsigned al2 = *(const unsigned*)&Al[r + 8];
            unsigned al3 = *(const unsigned*)&Al[r + 8 * FCSTR + 8];
            #pragma unroll
            for (int nf = 0; nf < 4; nf++) {
                mma_bf16(acc[mf][nf], ah0, ah1, ah2, ah3, bh[nf][0], bh[nf][1]);
                mma_bf16(acc[mf][nf], ah0, ah1, ah2, ah3, bl[nf][0], bl[nf][1]);
                mma_bf16(acc[mf][nf], al0, al1, al2, al3, bh[nf][0], bh[nf][1]);
            }
        }
        __syncthreads();
    }

    // epilogue
    #pragma unroll
    for (int nf = 0; nf < 4; nf++) {
        const int col = n0 + nbase + nf * 8 + t4 * 2;
        const float2 bias = *(const float2*)&fcb[col];
        #pragma unroll
        for (int mf = 0; mf < 4; mf++) {
            const int r0 = m0 + mbase + mf * 16 + g;
            float2 v0, v1;
            v0.x = acc[mf][nf][0] + bias.x;  v0.y = acc[mf][nf][1] + bias.y;
            v1.x = acc[mf][nf][2] + bias.x;  v1.y = acc[mf][nf][3] + bias.y;
            *(float2*)&out[(long long)r0 * VV + col]       = v0;
            *(float2*)&out[(long long)(r0 + 8) * VV + col] = v1;
        }
    }
}

// ---------------- launch ----------------------------------------------------
extern "C" void kernel_launch(void* const* d_in, const int* in_sizes, int n_in,
                              void* d_out, int out_size) {
    (void)in_sizes; (void)n_in; (void)out_size;
    const float* features = (const float*)d_in[0];
    const int*   captions = (const int*)  d_in[1];
    const float* embed    = (const float*)d_in[2];
    const float* WihS     = (const float*)d_in[3];
    const float* WhhS     = (const float*)d_in[4];
    const float* bihS     = (const float*)d_in[5];
    const float* bhhS     = (const float*)d_in[6];
    const float* WihU     = (const float*)d_in[7];
    const float* WhhU     = (const float*)d_in[8];
    const float* bihU     = (const float*)d_in[9];
    const float* bhhU     = (const float*)d_in[10];
    const float* fcW      = (const float*)d_in[11];
    const float* fcb      = (const float*)d_in[12];
    const float* szW      = (const float*)d_in[13];
    const float* szb      = (const float*)d_in[14];
    const float* wuW      = (const float*)d_in[15];
    const float* wub      = (const float*)d_in[16];
    float* out = (float*)d_out;

    pack_kernel<<<2048, 256>>>(WihS, WhhS, bihS, bhhS, WihU, WhhU, bihU, bhhU, fcW);
    init_kernel<<<BB, 256>>>(features, embed, szW, szb);
    steps_kernel<<<NBS, 128>>>(captions, embed, wuW, wub);
    fc_kernel<<<dim3(VV / 128, (TT * BB) / 128), 256>>>(fcb, out);
}

// round 7
// speedup vs baseline: 2.1864x; 1.1423x over previous
#include <cuda_runtime.h>
#include <cuda_bf16.h>
#include <math.h>

// Problem constants
#define VV    32000
#define EE    256
#define DD    25
#define BB    64
#define TT    24
#define HH    625          // D*D
#define INDIM 906          // E + H + D
#define KTOT  1556         // IN + H(hS) + D(hU)
#define KP    1600         // padded K for gate GEMM
#define NG    2600         // 4H + 4D real gate rows
#define NGP   2624         // padded to 82*32
#define NSTEPS 23
#define KFC   640          // padded 625 for final GEMM
#define NBS   82           // persistent blocks for steps (82 n32-tiles)

// ---------------- static device scratch (zero-initialized at load) ----------
__device__ unsigned short g_Wh[NGP * KP];     // gate weights bf16 hi (pad rows/cols = 0)
__device__ unsigned short g_Wl[NGP * KP];     // gate weights bf16 lo
__device__ float g_bias[NG];
__device__ unsigned short g_fcWh[VV * KFC];   // fcW bf16 hi
__device__ unsigned short g_fcWl[VV * KFC];   // fcW bf16 lo
__device__ unsigned short g_xhh[BB * KP];     // xh bf16 hi [cU|word|cS|hS|hU|pad]
__device__ unsigned short g_xhl[BB * KP];     // xh bf16 lo
__device__ float g_G[BB * NGP];               // gate pre-activations
__device__ float g_cS[BB * HH];
__device__ float g_cU[BB * DD];
__device__ unsigned short g_fth[TT * BB * KFC];  // ft bf16 hi (t=0 + pad stay 0)
__device__ unsigned short g_ftl[TT * BB * KFC];  // ft bf16 lo
__device__ unsigned int g_bar;

__device__ __forceinline__ float sigmoidf_(float x) {
    return __fdividef(1.f, 1.f + __expf(-x));
}
__device__ __forceinline__ float tanhf_(float x) {
    return 1.f - __fdividef(2.f, 1.f + __expf(2.f * x));
}

__device__ __forceinline__ unsigned short f2bf(float v) {
    __nv_bfloat16 b = __float2bfloat16(v);
    return *reinterpret_cast<unsigned short*>(&b);
}
__device__ __forceinline__ float bf2f(unsigned short u) {
    __nv_bfloat16 b;
    *reinterpret_cast<unsigned short*>(&b) = u;
    return __bfloat162float(b);
}
__device__ __forceinline__ void wr_xh(int b, int idx, float v) {
    unsigned short h = f2bf(v);
    g_xhh[b * KP + idx] = h;
    g_xhl[b * KP + idx] = f2bf(v - bf2f(h));
}

__device__ __forceinline__ void grid_sync_() {
    __syncthreads();
    if (threadIdx.x == 0) {
        __threadfence();
        unsigned int t = atomicAdd(&g_bar, 1u);
        unsigned int target = t - (t % NBS) + NBS;
        volatile unsigned int* p = &g_bar;
        while ((int)(*p - target) < 0) { }
    }
    __syncthreads();
}

__device__ __forceinline__ void cp16(void* sdst, const void* gsrc) {
    unsigned saddr = (unsigned)__cvta_generic_to_shared(sdst);
    asm volatile("cp.async.cg.shared.global [%0], [%1], 16;" :: "r"(saddr), "l"(gsrc));
}

__device__ __forceinline__ void mma_bf16(float c[4], unsigned a0, unsigned a1,
                                         unsigned a2, unsigned a3,
                                         unsigned b0, unsigned b1) {
    asm volatile(
        "mma.sync.aligned.m16n8k16.row.col.f32.bf16.bf16.f32 "
        "{%0,%1,%2,%3},{%4,%5,%6,%7},{%8,%9},{%0,%1,%2,%3};"
        : "+f"(c[0]), "+f"(c[1]), "+f"(c[2]), "+f"(c[3])
        : "r"(a0), "r"(a1), "r"(a2), "r"(a3), "r"(b0), "r"(b1));
}

__device__ __forceinline__ void ldsm4(unsigned& r0, unsigned& r1, unsigned& r2,
                                      unsigned& r3, const unsigned short* p) {
    unsigned a = (unsigned)__cvta_generic_to_shared(p);
    asm volatile("ldmatrix.sync.aligned.m8n8.x4.shared.b16 {%0,%1,%2,%3},[%4];"
                 : "=r"(r0), "=r"(r1), "=r"(r2), "=r"(r3) : "r"(a));
}

// ---------------- weight packing -------------------------------------------
__global__ void pack_kernel(const float* __restrict__ WihS, const float* __restrict__ WhhS,
                            const float* __restrict__ bihS, const float* __restrict__ bhhS,
                            const float* __restrict__ WihU, const float* __restrict__ WhhU,
                            const float* __restrict__ bihU, const float* __restrict__ bhhU,
                            const float* __restrict__ fcW) {
    const long long n_wcat = (long long)NGP * KP;
    const long long n_fc   = (long long)VV * KFC;
    const long long total  = n_wcat + n_fc + NG;
    for (long long i = blockIdx.x * (long long)blockDim.x + threadIdx.x; i < total;
         i += (long long)gridDim.x * blockDim.x) {
        if (i < n_wcat) {
            int n = (int)(i / KP), k = (int)(i % KP);
            float v = 0.f;
            if (n < 4 * HH) {
                if (k < INDIM)            v = WihS[n * INDIM + k];
                else if (k < INDIM + HH)  v = WhhS[n * HH + (k - INDIM)];
            } else if (n < NG) {
                int nu = n - 4 * HH;
                if (k < INDIM)                          v = WihU[nu * INDIM + k];
                else if (k >= INDIM + HH && k < KTOT)   v = WhhU[nu * DD + (k - INDIM - HH)];
            }
            unsigned short h = f2bf(v);
            g_Wh[i] = h;
            g_Wl[i] = f2bf(v - bf2f(h));
        } else if (i < n_wcat + n_fc) {
            long long j = i - n_wcat;
            int k = (int)(j % KFC);
            int n = (int)(j / KFC);
            float v = (k < HH) ? fcW[(long long)n * HH + k] : 0.f;
            unsigned short h = f2bf(v);
            g_fcWh[j] = h;
            g_fcWl[j] = f2bf(v - bf2f(h));
        } else {
            int n = (int)(i - n_wcat - n_fc);
            g_bias[n] = (n < 4 * HH) ? (bihS[n] + bhhS[n]) : (bihU[n - 4 * HH] + bhhU[n - 4 * HH]);
        }
    }
}

// ---------------- initial state --------------------------------------------
__global__ void init_kernel(const float* __restrict__ features, const float* __restrict__ embed,
                            const float* __restrict__ szW, const float* __restrict__ szb) {
    __shared__ float sf[EE];
    const int b = blockIdx.x, tid = threadIdx.x;
    sf[tid] = features[b * EE + tid];
    __syncthreads();
    for (int c = tid; c < HH; c += 256) {
        float acc = szb[c];
        const float* w = szW + c * EE;
        #pragma unroll 8
        for (int k = 0; k < EE; k++) acc += sf[k] * w[k];
        g_cS[b * HH + c] = acc;
        wr_xh(b, 281 + c, acc);   // cS slot
        wr_xh(b, 906 + c, 0.f);   // hS = 0
    }
    if (tid < DD) {
        g_cU[b * DD + tid] = 0.f;
        wr_xh(b, tid, 0.f);          // cU = 0
        wr_xh(b, 1531 + tid, 0.f);   // hU = 0
    }
    wr_xh(b, 25 + tid, embed[tid]);  // word0
}

// ---------------- persistent recurrence ------------------------------------
// 82 blocks x 128 threads. Phase A: tensor-core gate GEMM G = xh @ Wcat^T,
// block = 64x32 output tile (n32), 4 warps = k-split 4 (K=400 each), in-block
// reduce. Phase B: blocks 0..63 apply LSTM cells per batch, rebuild xh (bf16
// hi/lo), compute ft.
__global__ void __launch_bounds__(128)
steps_kernel(const int* __restrict__ captions, const float* __restrict__ embed,
             const float* __restrict__ wuW, const float* __restrict__ wub) {
    __shared__ float sred[4][2048];
    __shared__ float shS[HH];
    __shared__ float shU[DD];
    __shared__ float sut[HH];

    const int tid  = threadIdx.x;
    const int lane = tid & 31;
    const int w    = tid >> 5;       // warp = k-split index
    const int g    = lane >> 2;
    const int t4   = lane & 3;
    const int n0   = blockIdx.x * 32;
    const int k0w  = w * 400;

    for (int s = 0; s < NSTEPS; s++) {
        // ---------- phase A: tensor-core gate GEMM ----------
        float acc[4][4][4];
        #pragma unroll
        for (int mf = 0; mf < 4; mf++)
            #pragma unroll
            for (int nf = 0; nf < 4; nf++)
                #pragma unroll
                for (int r = 0; r < 4; r++) acc[mf][nf][r] = 0.f;

        for (int it = 0; it < 25; it++) {
            const int k = k0w + it * 16;
            unsigned ah[4][4], al[4][4];
            #pragma unroll
            for (int mf = 0; mf < 4; mf++) {
                const int r0 = (mf * 16 + g) * KP + k + 2 * t4;
                const int r1 = r0 + 8 * KP;
                ah[mf][0] = __ldcg((const unsigned*)(g_xhh + r0));
                ah[mf][1] = __ldcg((const unsigned*)(g_xhh + r1));
                ah[mf][2] = __ldcg((const unsigned*)(g_xhh + r0 + 8));
                ah[mf][3] = __ldcg((const unsigned*)(g_xhh + r1 + 8));
                al[mf][0] = __ldcg((const unsigned*)(g_xhl + r0));
                al[mf][1] = __ldcg((const unsigned*)(g_xhl + r1));
                al[mf][2] = __ldcg((const unsigned*)(g_xhl + r0 + 8));
                al[mf][3] = __ldcg((const unsigned*)(g_xhl + r1 + 8));
            }
            unsigned bh[4][2], bl[4][2];
            #pragma unroll
            for (int nf = 0; nf < 4; nf++) {
                const long long rb = (long long)(n0 + nf * 8 + g) * KP + k + 2 * t4;
                bh[nf][0] = *(const unsigned*)(g_Wh + rb);
                bh[nf][1] = *(const unsigned*)(g_Wh + rb + 8);
                bl[nf][0] = *(const unsigned*)(g_Wl + rb);
                bl[nf][1] = *(const unsigned*)(g_Wl + rb + 8);
            }
            #pragma unroll
            for (int mf = 0; mf < 4; mf++)
                #pragma unroll
                for (int nf = 0; nf < 4; nf++) {
                    mma_bf16(acc[mf][nf], ah[mf][0], ah[mf][1], ah[mf][2], ah[mf][3], bh[nf][0], bh[nf][1]);
                    mma_bf16(acc[mf][nf], ah[mf][0], ah[mf][1], ah[mf][2], ah[mf][3], bl[nf][0], bl[nf][1]);
                    mma_bf16(acc[mf][nf], al[mf][0], al[mf][1], al[mf][2], al[mf][3], bh[nf][0], bh[nf][1]);
                }
        }
        // in-block k-split reduction
        #pragma unroll
        for (int mf = 0; mf < 4; mf++)
            #pragma unroll
            for (int nf = 0; nf < 4; nf++)
                #pragma unroll
                for (int r = 0; r < 4; r++) {
                    int m  = mf * 16 + g + ((r >> 1) << 3);
                    int nl = nf * 8 + 2 * t4 + (r & 1);
                    sred[w][m * 32 + nl] = acc[mf][nf][r];
                }
        __syncthreads();
        #pragma unroll
        for (int e4 = 0; e4 < 4; e4++) {
            int e = tid * 4 + e4 * 512;
            float4 v0 = *(float4*)&sred[0][e];
            float4 v1 = *(float4*)&sred[1][e];
            float4 v2 = *(float4*)&sred[2][e];
            float4 v3 = *(float4*)&sred[3][e];
            float4 sOut;
            sOut.x = v0.x + v1.x + v2.x + v3.x;
            sOut.y = v0.y + v1.y + v2.y + v3.y;
            sOut.z = v0.z + v1.z + v2.z + v3.z;
            sOut.w = v0.w + v1.w + v2.w + v3.w;
            int m = e >> 5, nl = e & 31;
            *(float4*)&g_G[m * NGP + n0 + nl] = sOut;
        }
        grid_sync_();

        // ---------- phase B ----------
        if (blockIdx.x < BB) {
            const int b = blockIdx.x;
            const float* p = g_G + b * NGP;
            for (int e = tid; e < HH; e += 128) {
                float gi = __ldcg(p + e)        + g_bias[e];
                float gf = __ldcg(p + HH + e)   + g_bias[HH + e];
                float gg = __ldcg(p + 2*HH + e) + g_bias[2*HH + e];
                float go = __ldcg(p + 3*HH + e) + g_bias[3*HH + e];
                float c = sigmoidf_(gf) * g_cS[b * HH + e] + sigmoidf_(gi) * tanhf_(gg);
                float h = sigmoidf_(go) * tanhf_(c);
                g_cS[b * HH + e] = c;
                shS[e] = h;
                wr_xh(b, 281 + e, c);   // cS for next step
                wr_xh(b, 906 + e, h);   // hS
            }
            if (tid < DD) {
                const int e = tid, u = 4 * HH;
                float gi = __ldcg(p + u + e)      + g_bias[u + e];
                float gf = __ldcg(p + u + 25 + e) + g_bias[u + 25 + e];
                float gg = __ldcg(p + u + 50 + e) + g_bias[u + 50 + e];
                float go = __ldcg(p + u + 75 + e) + g_bias[u + 75 + e];
                float c = sigmoidf_(gf) * g_cU[b * DD + e] + sigmoidf_(gi) * tanhf_(gg);
                float h = sigmoidf_(go) * tanhf_(c);
                g_cU[b * DD + e] = c;
                shU[e] = h;
                wr_xh(b, e, c);          // cU
                wr_xh(b, 1531 + e, h);   // hU
            }
            if (s + 1 < NSTEPS) {
                const int wd = captions[b * TT + (s + 1)];
                for (int e = tid; e < EE; e += 128) wr_xh(b, 25 + e, embed[wd * EE + e]);
            }
            __syncthreads();
            for (int pp = tid; pp < HH; pp += 128) {   // ut = hU @ wuW.T + wub
                float acc2 = wub[pp];
                const float* r = wuW + pp * DD;
                #pragma unroll
                for (int d2 = 0; d2 < DD; d2++) acc2 += shU[d2] * r[d2];
                sut[pp] = acc2;
            }
            __syncthreads();
            const long long base = (long long)((s + 1) * BB + b) * KFC;
            for (int idx = tid; idx < HH; idx += 128) {  // ft = ut @ m2
                int i2 = idx / DD, j2 = idx - i2 * DD;
                float acc2 = 0.f;
                #pragma unroll
                for (int k2 = 0; k2 < DD; k2++) acc2 += sut[i2 * DD + k2] * shS[k2 * DD + j2];
                unsigned short h = f2bf(acc2);
                g_fth[base + idx] = h;
                g_ftl[base + idx] = f2bf(acc2 - bf2f(h));
            }
        }
        grid_sync_();
    }
}

// ---------------- final projection on tensor cores --------------------------
// out[m,n] = ft[m,:] . fcW[n,:] + fcb[n], bf16 hi/lo 3-term mma, ldmatrix loads.
#define FCSTR 24   // smem row stride in bf16 (48B: 16B-aligned, conflict-free LDSM)
__global__ void __launch_bounds__(256, 2)
fc_kernel(const float* __restrict__ fcb, float* __restrict__ out) {
    __shared__ unsigned short sAh[2][128 * FCSTR];
    __shared__ unsigned short sAl[2][128 * FCSTR];
    __shared__ unsigned short sBh[2][128 * FCSTR];
    __shared__ unsigned short sBl[2][128 * FCSTR];

    const int tid   = threadIdx.x;
    const int lane  = tid & 31;
    const int wid   = tid >> 5;
    const int g     = lane >> 2;
    const int t4    = lane & 3;
    const int mbase = (wid & 1) * 64;
    const int nbase = (wid >> 1) * 32;
    const int m0    = blockIdx.y * 128;
    const int n0    = blockIdx.x * 128;

    const int lrow  = tid >> 1;
    const int lks   = (tid & 1) * 8;

    // ldmatrix per-lane smem offsets (in shorts) within a buffer
    const int apos = (mbase + (lane & 15)) * FCSTR + (lane >> 4) * 8;
    const int bpos = (nbase + ((lane >> 4) & 1) * 8 + (lane & 7)) * FCSTR + ((lane >> 3) & 1) * 8;

    float acc[4][4][4];
    #pragma unroll
    for (int mf = 0; mf < 4; mf++)
        #pragma unroll
        for (int nf = 0; nf < 4; nf++)
            #pragma unroll
            for (int r = 0; r < 4; r++) acc[mf][nf][r] = 0.f;

    const unsigned short* gAh = g_fth + (long long)(m0 + lrow) * KFC + lks;
    const unsigned short* gAl = g_ftl + (long long)(m0 + lrow) * KFC + lks;
    const unsigned short* gBh = g_fcWh + (long long)(n0 + lrow) * KFC + lks;
    const unsigned short* gBl = g_fcWl + (long long)(n0 + lrow) * KFC + lks;
    const int sOff = lrow * FCSTR + lks;

    cp16(&sAh[0][sOff], gAh);
    cp16(&sAl[0][sOff], gAl);
    cp16(&sBh[0][sOff], gBh);
    cp16(&sBl[0][sOff], gBl);
    asm volatile("cp.async.commit_group;");

    for (int ch = 0; ch < 40; ch++) {
        if (ch < 39) {
            const int k0 = (ch + 1) * 16;
            const int buf = (ch + 1) & 1;
            cp16(&sAh[buf][sOff], gAh + k0);
            cp16(&sAl[buf][sOff], gAl + k0);
            cp16(&sBh[buf][sOff], gBh + k0);
            cp16(&sBl[buf][sOff], gBl + k0);
            asm volatile("cp.async.commit_group;");
            asm volatile("cp.async.wait_group 1;" ::: "memory");
        } else {
            asm volatile("cp.async.wait_group 0;" ::: "memory");
        }
        __syncthreads();

        const int buf = ch & 1;
        const unsigned short* Ah = sAh[buf];
        const unsigned short* Al = sAl[buf];
        const unsigned short* Bh = sBh[buf];
        const unsigned short* Bl = sBl[buf];

        unsigned bh[4][2], bl[4][2];
        ldsm4(bh[0][0], bh[0][1], bh[1][0], bh[1][1], Bh + bpos);
        ldsm4(bh[2][0], bh[2][1], bh[3][0], bh[3][1], Bh + bpos + 16 * FCSTR);
        ldsm4(bl[0][0], bl[0][1], bl[1][0], bl[1][1], Bl + bpos);
        ldsm4(bl[2][0], bl[2][1], bl[3][0], bl[3][1], Bl + bpos + 16 * FCSTR);

        #pragma unroll
        for (int mf = 0; mf < 4; mf++) {
            unsigned ah0, ah1, ah2, ah3, al0, al1, al2, al3;
            ldsm4(ah0, ah1, ah2, ah3, Ah + apos + mf * 16 * FCSTR);
            ldsm4(al0, al1, al2, al3, Al + apos + mf * 16 * FCSTR);
            #pragma unroll
            for (int nf = 0; nf < 4; nf++) {
                mma_bf16(acc[mf][nf], ah0, ah1, ah2, ah3, bh[nf][0], bh[nf][1]);
                mma_bf16(acc[mf][nf], ah0, ah1, ah2, ah3, bl[nf][0], bl[nf][1]);
                mma_bf16(acc[mf][nf], al0, al1, al2, al3, bh[nf][0], bh[nf][1]);
            }
        }
        __syncthreads();
    }

    #pragma unroll
    for (int nf = 0; nf < 4; nf++) {
        const int col = n0 + nbase + nf * 8 + t4 * 2;
        const float2 bias = *(const float2*)&fcb[col];
        #pragma unroll
        for (int mf = 0; mf < 4; mf++) {
            const int r0 = m0 + mbase + mf * 16 + g;
            float2 v0, v1;
            v0.x = acc[mf][nf][0] + bias.x;  v0.y = acc[mf][nf][1] + bias.y;
            v1.x = acc[mf][nf][2] + bias.x;  v1.y = acc[mf][nf][3] + bias.y;
            *(float2*)&out[(long long)r0 * VV + col]       = v0;
            *(float2*)&out[(long long)(r0 + 8) * VV + col] = v1;
        }
    }
}

// ---------------- launch ----------------------------------------------------
extern "C" void kernel_launch(void* const* d_in, const int* in_sizes, int n_in,
                              void* d_out, int out_size) {
    (void)in_sizes; (void)n_in; (void)out_size;
    const float* features = (const float*)d_in[0];
    const int*   captions = (const int*)  d_in[1];
    const float* embed    = (const float*)d_in[2];
    const float* WihS     = (const float*)d_in[3];
    const float* WhhS     = (const float*)d_in[4];
    const float* bihS     = (const float*)d_in[5];
    const float* bhhS     = (const float*)d_in[6];
    const float* WihU     = (const float*)d_in[7];
    const float* WhhU     = (const float*)d_in[8];
    const float* bihU     = (const float*)d_in[9];
    const float* bhhU     = (const float*)d_in[10];
    const float* fcW      = (const float*)d_in[11];
    const float* fcb      = (const float*)d_in[12];
    const float* szW      = (const float*)d_in[13];
    const float* szb      = (const float*)d_in[14];
    const float* wuW      = (const float*)d_in[15];
    const float* wub      = (const float*)d_in[16];
    float* out = (float*)d_out;

    pack_kernel<<<2048, 256>>>(WihS, WhhS, bihS, bhhS, WihU, WhhU, bihU, bhhU, fcW);
    init_kernel<<<BB, 256>>>(features, embed, szW, szb);
    steps_kernel<<<NBS, 128>>>(captions, embed, wuW, wub);
    fc_kernel<<<dim3(VV / 128, (TT * BB) / 128), 256>>>(fcb, out);
}